// round 10
// baseline (speedup 1.0000x reference)
#include <cuda_runtime.h>
#include <cuda_fp16.h>
#include <cstdint>

// Problem constants
#define B_  32
#define N_  4096
#define E_  8192
#define D_  128
#define ROWS_TOTAL (B_*N_)        // 131072
#define NEDGE (B_*E_)             // 262144
#define NTILES (ROWS_TOTAL/64)    // 2048
#define GRIDP 304                 // persistent grid: 2 CTAs x 152 SMs

// ---------------- device-global scratch ------------------------------------------
__device__ __half g_agg[B_*N_*D_];         // 32MB fp16 aggregation buffer
__device__ __half g_wt[2*384*128];         // transposed fp16 weights: [mat][col(384)][k(128)]

// ---------------- smem layout (bytes), per 64-row CTA ----------------------------
// fp16 tiles: [rows][136 halves] (8-half pad -> 272B row stride, ldmatrix clean).
#define OFF_BIAS  0                 // 768 floats (3072 B)
#define OFF_AG    3072              // agg fp16 tile 64x272  (17408 B)
#define OFF_AH    20480             // h   fp16 tile 64x272  (17408 B)
#define OFF_B0    37888             // B ring buf 0 128x272  (34816 B)
#define OFF_B1    72704             // B ring buf 1 128x272  (34816 B)
#define SMEM_TOTAL 107520           // < 113.5KB -> 2 CTAs/SM

__device__ __forceinline__ uint32_t smem_u32(const void* p) {
    uint32_t a;
    asm("{ .reg .u64 t; cvta.to.shared.u64 t, %1; cvt.u32.u64 %0, t; }" : "=r"(a) : "l"(p));
    return a;
}

__device__ __forceinline__ void ldsm4(uint32_t d[4], uint32_t addr) {
    asm volatile("ldmatrix.sync.aligned.m8n8.x4.shared.b16 {%0,%1,%2,%3}, [%4];"
                 : "=r"(d[0]), "=r"(d[1]), "=r"(d[2]), "=r"(d[3]) : "r"(addr));
}

__device__ __forceinline__ void mma_16816(float c[4], const uint32_t a[4], uint32_t b0, uint32_t b1) {
    asm volatile(
        "mma.sync.aligned.m16n8k16.row.col.f32.f16.f16.f32 "
        "{%0,%1,%2,%3}, {%4,%5,%6,%7}, {%8,%9}, {%0,%1,%2,%3};"
        : "+f"(c[0]), "+f"(c[1]), "+f"(c[2]), "+f"(c[3])
        : "r"(a[0]), "r"(a[1]), "r"(a[2]), "r"(a[3]), "r"(b0), "r"(b1));
}

__device__ __forceinline__ float tanh_ap(float x) {
    float y;
    asm("tanh.approx.f32 %0, %1;" : "=f"(y) : "f"(x));
    return y;
}
__device__ __forceinline__ float sigf(float x) { return fmaf(0.5f, tanh_ap(0.5f * x), 0.5f); }

#define CP_ASYNC16(dst, src) \
    asm volatile("cp.async.cg.shared.global [%0], [%1], 16;" :: "r"(dst), "l"(src) : "memory")
#define CP_COMMIT() asm volatile("cp.async.commit_group;" ::: "memory")
#define CP_WAIT(n)  asm volatile("cp.async.wait_group %0;" :: "n"(n) : "memory")

// ================================================================================
// Kernel 1: transpose + fp16-convert weights:  g_wt[mat][col][k] = W[k*384+col]
// ================================================================================
__global__ void prep_w_kernel(const float* __restrict__ kern, const float* __restrict__ rker) {
    int i = blockIdx.x * blockDim.x + threadIdx.x;
    if (i >= 2 * 384 * 128) return;
    int mat = i / (384 * 128);
    int rem = i - mat * (384 * 128);
    int col = rem >> 7;
    int k   = rem & 127;
    const float* W = mat ? rker : kern;
    g_wt[i] = __float2half_rn(W[k * 384 + col]);
}

// ================================================================================
// Kernel 2: zero the fp16 aggregation scratch (32MB)
// ================================================================================
__global__ void zero_agg_kernel() {
    const uint4 z = make_uint4(0u, 0u, 0u, 0u);
    int n16 = (B_ * N_ * D_ * 2) / 16;
    for (int i = blockIdx.x * blockDim.x + threadIdx.x; i < n16; i += gridDim.x * blockDim.x)
        reinterpret_cast<uint4*>(g_agg)[i] = z;
}

// ================================================================================
// Kernel 3: scatter-add into fp16 g_agg.  2 edges/warp, 16 lanes/edge,
// v4.f16x2 (16B) vector reduction.
// ================================================================================
__global__ void scatter_kernel(const float* __restrict__ msgs, const int* __restrict__ conn) {
    int gwarp = (blockIdx.x * blockDim.x + threadIdx.x) >> 5;
    int lane  = threadIdx.x & 31;
    int edge  = gwarp * 2 + (lane >> 4);
    if (edge >= NEDGE) return;
    int sub   = lane & 15;
    int b     = edge >> 13;

    int tgt;
    if (sub == 0) tgt = conn[edge * 2 + 1];
    tgt = __shfl_sync(0xffffffffu, tgt, lane & 16);

    const float4* mp = reinterpret_cast<const float4*>(msgs) + (size_t)edge * 32 + sub * 2;
    float4 m0 = mp[0];
    float4 m1 = mp[1];
    union { __half2 h; uint32_t u; } p0, p1, p2, p3;
    p0.h = __floats2half2_rn(m0.x, m0.y);
    p1.h = __floats2half2_rn(m0.z, m0.w);
    p2.h = __floats2half2_rn(m1.x, m1.y);
    p3.h = __floats2half2_rn(m1.z, m1.w);
    __half* dst = g_agg + ((size_t)((b << 12) + tgt)) * 128 + sub * 8;
    asm volatile("red.global.add.noftz.v4.f16x2 [%0], {%1, %2, %3, %4};"
                 :: "l"(dst), "r"(p0.u), "r"(p1.u), "r"(p2.u), "r"(p3.u) : "memory");
}

// ================================================================================
// Kernel 4: persistent fused dual-GEMM + GRU epilogue.
// 304 CTAs, 256 threads (8 warps, 2x4 grid, warp tile 32x32), ~7 tiles each.
// Continuous 6-phase cp.async B ring across tiles; AG via cp.async; h via LDG
// staged in the previous tile's epilogue slot.
// ================================================================================

// phase -> (mat, gate):  p0:Wx_z p1:Wh_z p2:Wx_r p3:Wh_r p4:Wh_h p5:Wx_h
__device__ __forceinline__ void prefetch_B(uint32_t dstbase, int phase, int tid) {
    const int matv = (0x1A >> phase) & 1;         // 0,1,0,1,1,0
    const int gv   = phase >> 1;                  // 0,0,1,1,2,2
    const char* src = reinterpret_cast<const char*>(
        g_wt + (size_t)(matv * 384 + gv * 128) * 128);
#pragma unroll
    for (int k = 0; k < 8; k++) {
        int c = tid + k * 256;
        uint32_t dst = dstbase + (uint32_t)((c >> 4) * 272 + (c & 15) * 16);
        CP_ASYNC16(dst, src + (size_t)c * 16);
    }
    CP_COMMIT();
}

__device__ __forceinline__ void prefetch_A_agg(uint32_t dstbase, const __half* src, int tid) {
    const char* s = reinterpret_cast<const char*>(src);
#pragma unroll
    for (int k = 0; k < 4; k++) {
        int c = tid + k * 256;
        uint32_t dst = dstbase + (uint32_t)((c >> 4) * 272 + (c & 15) * 16);
        CP_ASYNC16(dst, s + (size_t)c * 16);
    }
    CP_COMMIT();
}

// h tile: fp32 LDG -> fp16 convert -> STS (visible after next barrier)
__device__ __forceinline__ void stage_h(char* smem, const float* __restrict__ atom_state,
                                        int row0, int tid) {
    const float4* hp = reinterpret_cast<const float4*>(atom_state + (size_t)row0 * 128);
    float4 hv[8];
#pragma unroll
    for (int k = 0; k < 8; k++)
        hv[k] = hp[tid + k * 256];
#pragma unroll
    for (int k = 0; k < 8; k++) {
        int idx = tid + k * 256;
        int row = idx >> 5;
        int f4  = idx & 31;
        union { __half2 h2[2]; uint2 u; } cv;
        cv.h2[0] = __floats2half2_rn(hv[k].x, hv[k].y);
        cv.h2[1] = __floats2half2_rn(hv[k].z, hv[k].w);
        *reinterpret_cast<uint2*>(smem + OFF_AH + row * 272 + f4 * 8) = cv.u;
    }
}

__device__ __forceinline__ void gemm_into(float (&acc)[2][4][4], uint32_t aBase, uint32_t bBase) {
#pragma unroll
    for (int kc = 0; kc < 4; kc++) {
        uint32_t A[2][2][4];
        uint32_t Bf[4][4];
#pragma unroll
        for (int mt = 0; mt < 2; mt++) {
            ldsm4(A[mt][0], aBase + mt * 4352 + kc * 64);
            ldsm4(A[mt][1], aBase + mt * 4352 + kc * 64 + 32);
        }
#pragma unroll
        for (int nt = 0; nt < 4; nt++)
            ldsm4(Bf[nt], bBase + nt * 2176 + kc * 64);
#pragma unroll
        for (int mt = 0; mt < 2; mt++)
#pragma unroll
            for (int nt = 0; nt < 4; nt++) {
                mma_16816(acc[mt][nt], A[mt][0], Bf[nt][0], Bf[nt][1]);
                mma_16816(acc[mt][nt], A[mt][1], Bf[nt][2], Bf[nt][3]);
            }
    }
}

#define ZERO_ACC() do { _Pragma("unroll") \
    for (int mt = 0; mt < 2; mt++) _Pragma("unroll") \
        for (int nt = 0; nt < 4; nt++) \
            acc[mt][nt][0] = acc[mt][nt][1] = acc[mt][nt][2] = acc[mt][nt][3] = 0.f; } while (0)

__global__ void __launch_bounds__(256, 2)
gru_gemm_kernel(const float* __restrict__ atom_state,
                const float* __restrict__ bias,
                float* __restrict__ out)
{
    extern __shared__ char smem[];
    const uint32_t sb = smem_u32(smem);
    const int tid  = threadIdx.x;
    const int wid  = tid >> 5;
    const int lane = tid & 31;
    const int wr   = wid & 1;
    const int wc   = wid >> 1;

    float* bias_s = reinterpret_cast<float*>(smem + OFF_BIAS);

    int tile = blockIdx.x;
    if (tile >= NTILES) return;

    // ---- prolog prefetches for first tile: B(p0), AG, B(p1) ----
    prefetch_B(sb + OFF_B0, 0, tid);
    prefetch_A_agg(sb + OFF_AG, g_agg + (size_t)tile * 64 * 128, tid);
    prefetch_B(sb + OFF_B1, 1, tid);

    for (int i = tid; i < 768; i += 256) bias_s[i] = bias[i];
    stage_h(smem, atom_state, tile * 64, tid);

    // ---- per-lane ldmatrix address patterns ----
    const int g4  = lane >> 2;
    const int tig = lane & 3;
    const int t   = lane >> 3;
    const int r8  = lane & 7;
    const uint32_t aoff = (uint32_t)(((wr * 32 + (t & 1) * 8 + r8) * 136 + (t >> 1) * 8) * 2);
    const uint32_t boff = (uint32_t)(((wc * 32 + r8) * 136 + t * 8) * 2);
    const uint32_t aAg = sb + OFF_AG + aoff;
    const uint32_t aAh = sb + OFF_AH + aoff;
    const uint32_t bB0 = sb + OFF_B0 + boff;
    const uint32_t bB1 = sb + OFF_B1 + boff;

    float acc[2][4][4];
    __half2 zpk[2][4][2];
    __half2 rpk[2][4][2];

    for (; tile < NTILES; tile += GRIDP) {
        const int row0 = tile * 64;
        const int ntile = tile + GRIDP;
        const bool more = ntile < NTILES;

        // ============ phase 0: acc = agg @ Wx_z ============
        CP_WAIT(1);                        // B(p0) + AG done; B(p1) pending
        __syncthreads();
        ZERO_ACC();
        gemm_into(acc, aAg, bB0);
        __syncthreads();
        prefetch_B(sb + OFF_B0, 2, tid);

        // ============ phase 1: acc += h @ Wh_z -> z ============
        CP_WAIT(1);
        __syncthreads();
        gemm_into(acc, aAh, bB1);
        __syncthreads();
        prefetch_B(sb + OFF_B1, 3, tid);
#pragma unroll
        for (int mt = 0; mt < 2; mt++)
#pragma unroll
            for (int nt = 0; nt < 4; nt++) {
                int colb = wc * 32 + nt * 8 + tig * 2;
                float b0 = bias_s[colb]     + bias_s[384 + colb];
                float b1 = bias_s[colb + 1] + bias_s[384 + colb + 1];
                zpk[mt][nt][0] = __floats2half2_rn(sigf(acc[mt][nt][0] + b0), sigf(acc[mt][nt][1] + b1));
                zpk[mt][nt][1] = __floats2half2_rn(sigf(acc[mt][nt][2] + b0), sigf(acc[mt][nt][3] + b1));
            }

        // ============ phase 2: acc = agg @ Wx_r ============
        CP_WAIT(1);
        __syncthreads();
        ZERO_ACC();
        gemm_into(acc, aAg, bB0);
        __syncthreads();
        prefetch_B(sb + OFF_B0, 4, tid);

        // ============ phase 3: acc += h @ Wh_r -> r ============
        CP_WAIT(1);
        __syncthreads();
        gemm_into(acc, aAh, bB1);
        __syncthreads();
        prefetch_B(sb + OFF_B1, 5, tid);
#pragma unroll
        for (int mt = 0; mt < 2; mt++)
#pragma unroll
            for (int nt = 0; nt < 4; nt++) {
                int colb = wc * 32 + nt * 8 + tig * 2;
                float b0 = bias_s[128 + colb]     + bias_s[384 + 128 + colb];
                float b1 = bias_s[128 + colb + 1] + bias_s[384 + 128 + colb + 1];
                rpk[mt][nt][0] = __floats2half2_rn(sigf(acc[mt][nt][0] + b0), sigf(acc[mt][nt][1] + b1));
                rpk[mt][nt][1] = __floats2half2_rn(sigf(acc[mt][nt][2] + b0), sigf(acc[mt][nt][3] + b1));
            }

        // ============ phase 4: acc = h @ Wh_h ; r := r*(acc+b) ============
        CP_WAIT(1);
        __syncthreads();
        ZERO_ACC();
        gemm_into(acc, aAh, bB0);
        __syncthreads();
        prefetch_B(sb + OFF_B0, 0, tid);   // next tile's p0 (wasted if !more)
#pragma unroll
        for (int mt = 0; mt < 2; mt++)
#pragma unroll
            for (int nt = 0; nt < 4; nt++) {
                int colb = wc * 32 + nt * 8 + tig * 2;
                float b0 = bias_s[384 + 256 + colb];
                float b1 = bias_s[384 + 256 + colb + 1];
                float2 ra = __half22float2(rpk[mt][nt][0]);
                float2 rb = __half22float2(rpk[mt][nt][1]);
                rpk[mt][nt][0] = __floats2half2_rn(ra.x * (acc[mt][nt][0] + b0), ra.y * (acc[mt][nt][1] + b1));
                rpk[mt][nt][1] = __floats2half2_rn(rb.x * (acc[mt][nt][2] + b0), rb.y * (acc[mt][nt][3] + b1));
            }

        // ============ phase 5: acc = agg @ Wx_h ============
        CP_WAIT(1);
        __syncthreads();
        ZERO_ACC();
        gemm_into(acc, aAg, bB1);
        __syncthreads();                   // AG + B1 free
        if (more) prefetch_A_agg(sb + OFF_AG, g_agg + (size_t)ntile * 64 * 128, tid);
        else      CP_COMMIT();             // keep group ledger aligned
        prefetch_B(sb + OFF_B1, 1, tid);   // next tile's p1

        // ---- final epilogue: hh = tanh(xh + r*rh); out = z*h + (1-z)*hh ----
#pragma unroll
        for (int mt = 0; mt < 2; mt++) {
            const int lrow_a = wr * 32 + mt * 16 + g4;
            const int lrow_b = lrow_a + 8;
#pragma unroll
            for (int nt = 0; nt < 4; nt++) {
                int colb = wc * 32 + nt * 8 + tig * 2;
                float b0 = bias_s[256 + colb];
                float b1 = bias_s[256 + colb + 1];
                float2 tA = __half22float2(rpk[mt][nt][0]);
                float2 tB = __half22float2(rpk[mt][nt][1]);
                float2 zA = __half22float2(zpk[mt][nt][0]);
                float2 zB = __half22float2(zpk[mt][nt][1]);
                float2 hA = __half22float2(*reinterpret_cast<const __half2*>(
                    smem + OFF_AH + lrow_a * 272 + colb * 2));
                float2 hB = __half22float2(*reinterpret_cast<const __half2*>(
                    smem + OFF_AH + lrow_b * 272 + colb * 2));

                float hh0 = tanh_ap(acc[mt][nt][0] + b0 + tA.x);
                float hh1 = tanh_ap(acc[mt][nt][1] + b1 + tA.y);
                float hh2 = tanh_ap(acc[mt][nt][2] + b0 + tB.x);
                float hh3 = tanh_ap(acc[mt][nt][3] + b1 + tB.y);

                float2 oA = make_float2(zA.x * hA.x + (1.f - zA.x) * hh0,
                                        zA.y * hA.y + (1.f - zA.y) * hh1);
                float2 oB = make_float2(zB.x * hB.x + (1.f - zB.x) * hh2,
                                        zB.y * hB.y + (1.f - zB.y) * hh3);
                *reinterpret_cast<float2*>(out + (size_t)(row0 + lrow_a) * 128 + colb) = oA;
                *reinterpret_cast<float2*>(out + (size_t)(row0 + lrow_b) * 128 + colb) = oB;
            }
        }
        __syncthreads();                   // all AH reads done before restage
        if (more) stage_h(smem, atom_state, ntile * 64, tid);
        // (next iteration's phase-0 barrier publishes the new AH tile)
    }
}

// ================================================================================
// Launch
// ================================================================================
extern "C" void kernel_launch(void* const* d_in, const int* in_sizes, int n_in,
                              void* d_out, int out_size) {
    const float* atom_state = (const float*)d_in[0];
    const float* messages   = (const float*)d_in[1];
    const int*   conn       = (const int*)d_in[2];
    const float* kern       = (const float*)d_in[3];
    const float* rker       = (const float*)d_in[4];
    const float* bias       = (const float*)d_in[5];
    float* out = (float*)d_out;

    cudaFuncSetAttribute(gru_gemm_kernel, cudaFuncAttributeMaxDynamicSharedMemorySize, SMEM_TOTAL);

    prep_w_kernel<<<(2 * 384 * 128 + 255) / 256, 256>>>(kern, rker);
    zero_agg_kernel<<<2048, 256>>>();
    scatter_kernel<<<(NEDGE / 2 * 32) / 256, 256>>>(messages, conn);
    gru_gemm_kernel<<<GRIDP, 256, SMEM_TOTAL>>>(atom_state, bias, out);
}